// round 17
// baseline (speedup 1.0000x reference)
#include <cuda_runtime.h>
#include <cuda_fp16.h>
#include <cstdint>
#include <cstddef>

// Problem constants: B=4, S=4096 -> N=16384 tokens
#define N_TOK 16384
#define DIM   4096
#define OUT_D 4096
#define SCALING 0.5f
#define W1_N8 18   // 144 rows / 8: 16 A-blocks + router-hi + router-lo

// -------- static scratch, fp16 fragment-major (m16n8k16) --------
// GEMM1 B operand, interleaved per k32: [k32 0..127][n8 0..17][lane][4]
__device__ __align__(16) uint32_t g_w1f[128 * W1_N8 * 128];
// GEMM2 B operand: [n8 0..511][k16 0..7][lane*2 + reg]
__device__ __align__(16) uint32_t g_btf[512 * 8 * 64];
// GEMM2 A operand: [m16 0..1023][k16 0..7][lane*4 + reg]
__device__ __align__(16) uint32_t g_hwf[(size_t)1024 * 8 * 128];

// -------- helpers --------
__device__ __forceinline__ uint32_t pack_f16x2(float lo, float hi) {
    uint32_t r;   // d.low = 2nd src, d.high = 1st src
    asm("cvt.rn.f16x2.f32 %0, %1, %2;" : "=r"(r) : "f"(hi), "f"(lo));
    return r;
}
__device__ __forceinline__ float2 unpack_f16x2(uint32_t v) {
    __half2 h = *(__half2*)&v;
    return __half22float2(h);
}
__device__ __forceinline__ void mma_f16(float* c, const uint32_t* a,
                                        uint32_t b0, uint32_t b1) {
    asm volatile(
        "mma.sync.aligned.m16n8k16.row.col.f32.f16.f16.f32 "
        "{%0,%1,%2,%3}, {%4,%5,%6,%7}, {%8,%9}, {%0,%1,%2,%3};\n"
        : "+f"(c[0]), "+f"(c[1]), "+f"(c[2]), "+f"(c[3])
        : "r"(a[0]), "r"(a[1]), "r"(a[2]), "r"(a[3]), "r"(b0), "r"(b1));
}
__device__ __forceinline__ void cp16(void* dst, const void* src) {
    uint32_t d = (uint32_t)__cvta_generic_to_shared(dst);
    asm volatile("cp.async.cg.shared.global [%0], [%1], 16;" :: "r"(d), "l"(src));
}
__device__ __forceinline__ void cp8(void* dst, const void* src) {
    uint32_t d = (uint32_t)__cvta_generic_to_shared(dst);
    asm volatile("cp.async.ca.shared.global [%0], [%1], 8;" :: "r"(d), "l"(src));
}
#define CP_COMMIT() asm volatile("cp.async.commit_group;")
#define CP_WAIT(n)  asm volatile("cp.async.wait_group %0;" :: "n"(n))

// ============================================================================
// Prep: build fp16 fragment-major operand tensors once. (unchanged from R14)
// ============================================================================
__global__ void prep_kernel(const float* __restrict__ rw,
                            const float* __restrict__ A,
                            const float* __restrict__ Bm)
{
    const int nthr = gridDim.x * blockDim.x;
    const int tid0 = blockIdx.x * blockDim.x + threadIdx.x;
    for (int i = tid0; i < 144 * 2048; i += nthr) {
        int n = i >> 11, k = (i & 2047) * 2;
        float v0, v1;
        if (n < 128) {
            v0 = A[n * 4096 + k]; v1 = A[n * 4096 + k + 1];
        } else if (n < 136) {
            v0 = rw[(n - 128) * 4096 + k]; v1 = rw[(n - 128) * 4096 + k + 1];
        } else {
            float f0 = rw[(n - 136) * 4096 + k];
            float f1 = rw[(n - 136) * 4096 + k + 1];
            v0 = f0 - __half2float(__float2half_rn(f0));
            v1 = f1 - __half2float(__float2half_rn(f1));
        }
        int lane = (n & 7) * 4 + ((k & 7) >> 1);
        int idx = ((k >> 5) * W1_N8 + (n >> 3)) * 128
                + lane * 4 + ((k >> 4) & 1) * 2 + ((k >> 3) & 1);
        g_w1f[idx] = pack_f16x2(v0, v1);
    }
    for (int i = tid0; i < 4096 * 64; i += nthr) {
        int o = i >> 6, c = (i & 63) * 2;
        int e = c >> 4, r = c & 15;
        const float* bp = Bm + ((size_t)e * 4096 + o) * 16 + r;
        int idx = ((o >> 3) * 8 + (c >> 4)) * 64
                + ((o & 7) * 4 + ((c & 7) >> 1)) * 2 + ((c >> 3) & 1);
        g_btf[idx] = pack_f16x2(bp[0] * SCALING, bp[1] * SCALING);
    }
}

// ============================================================================
// GEMM1 (R14 structure: k64 stages, ring 4, 64 barriers, hoisted uint4 B).
// NEW: x staged via 8B cp.async in pair-grouped layout so consumer A-path is
// 2x LDS.128 per (ks,mt). word(row,p) = row*32 +
//   (((p&3) + 4*(p>>3)) ^ swz(row))*4 + ((p>>2)&1)*2,
//   swz(row) = ((row&1)<<2) | ((row>>1)&3).  Bitwise-identical math.
// ============================================================================
#define AT_WORDS  (128 * 32)
#define AS_STAGE  (2 * AT_WORDS)
#define AS_WORDS  (4 * AS_STAGE)
#define WT_WORDS  (W1_N8 * 128)           // one k32 W slab: 2304 words
#define WS_STAGE  (2 * WT_WORDS)
#define WS_WORDS  (4 * WS_STAGE)
#define SM1_WORDS (AS_WORDS + WS_WORDS + 1024 + 1024)

__global__ __launch_bounds__(256, 1)
void gemm1_kernel(const float* __restrict__ x, const float* __restrict__ rb)
{
    extern __shared__ uint32_t smu[];
    uint32_t* As   = smu;
    uint32_t* Ws   = smu + AS_WORDS;
    float*    gw   = (float*)(smu + AS_WORDS + WS_WORDS);
    float*    lbuf = (float*)(smu + AS_WORDS + WS_WORDS + 1024);

    const int tid  = threadIdx.x;
    const int lane = tid & 31;
    const int warp = tid >> 5;
    const int wm   = warp & 3;
    const int wn   = warp >> 2;
    const int g    = lane >> 2;
    const int tig  = lane & 3;
    const int m0   = blockIdx.x * 128;
    const int ncol0 = wn * 64;
    const int swz  = ((g & 1) << 2) | ((g >> 1) & 3);   // consumer slot swizzle

    float acc[2][9][4];
#pragma unroll
    for (int mt = 0; mt < 2; mt++)
#pragma unroll
        for (int nt = 0; nt < 9; nt++)
#pragma unroll
            for (int i = 0; i < 4; i++) acc[mt][nt][i] = 0.f;

    auto issue = [&](int stage, int u) {
        uint32_t* ab = As + stage * AS_STAGE;
        uint32_t* wb = Ws + stage * WS_STAGE;
#pragma unroll
        for (int sub = 0; sub < 2; ++sub) {
            const int t  = 2 * u + sub;
            const int k0 = t * 32;
            uint32_t* a = ab + sub * AT_WORDS;
            uint32_t* w = wb + sub * WT_WORDS;
#pragma unroll
            for (int i = 0; i < 8; i++) {
                int idx = tid + i * 256;           // 0..2047
                int row = idx >> 4, p = idx & 15;
                int sw  = ((row & 1) << 2) | ((row >> 1) & 3);
                int word = row * 32 + (((p & 3) + 4 * (p >> 3)) ^ sw) * 4
                         + ((p >> 2) & 1) * 2;
                cp8(a + word, x + (size_t)(m0 + row) * DIM + k0 + 2 * p);
            }
#pragma unroll
            for (int i = 0; i < 3; i++) {
                int idx = tid + i * 256;
                if (idx < 576)
                    cp16(w + idx * 4, g_w1f + (size_t)t * WT_WORDS + idx * 4);
            }
        }
    };

    issue(0, 0); CP_COMMIT();
    issue(1, 1); CP_COMMIT();
    issue(2, 2); CP_COMMIT();

    const int U = DIM / 64;
    for (int u = 0; u < U; ++u) {
        CP_WAIT(2);
        __syncthreads();
        if (u + 3 < U) issue((u + 3) & 3, u + 3);
        CP_COMMIT();

#pragma unroll
        for (int sub = 0; sub < 2; ++sub) {
            const int t = 2 * u + sub;
            const uint32_t* a = As + (u & 3) * AS_STAGE + sub * AT_WORDS;
            const uint32_t* w = Ws + (u & 3) * WS_STAGE + sub * WT_WORDS;
            const bool do_logits = (wn == (t & 1));

            // hoisted B fragments: one LDS.128 per n8 covers both k16 steps
            uint4 bb4[8];
#pragma unroll
            for (int nt = 0; nt < 8; ++nt)
                bb4[nt] = *(const uint4*)(w + (wn * 8 + nt) * 128 + lane * 4);
            uint4 bh4 = make_uint4(0, 0, 0, 0), bl4 = make_uint4(0, 0, 0, 0);
            if (do_logits) {
                bh4 = *(const uint4*)(w + 16 * 128 + lane * 4);
                bl4 = *(const uint4*)(w + 17 * 128 + lane * 4);
            }

#pragma unroll
            for (int ks = 0; ks < 2; ++ks) {
                const int soff = ((tig + 4 * ks) ^ swz) * 4;
                uint32_t af[2][4];
                float4 rawA[2], rawB[2];     // rawA: row r0; rawB: row r0+8
#pragma unroll
                for (int mt = 0; mt < 2; ++mt) {
                    const int r0 = wm * 32 + mt * 16 + g;
                    rawA[mt] = *(const float4*)(a + r0 * 32 + soff);
                    rawB[mt] = *(const float4*)(a + (r0 + 8) * 32 + soff);
                    af[mt][0] = pack_f16x2(rawA[mt].x, rawA[mt].y);
                    af[mt][1] = pack_f16x2(rawB[mt].x, rawB[mt].y);
                    af[mt][2] = pack_f16x2(rawA[mt].z, rawA[mt].w);
                    af[mt][3] = pack_f16x2(rawB[mt].z, rawB[mt].w);
                }
#pragma unroll
                for (int nt = 0; nt < 8; ++nt) {
                    uint32_t b0 = ks ? bb4[nt].z : bb4[nt].x;
                    uint32_t b1 = ks ? bb4[nt].w : bb4[nt].y;
                    mma_f16(acc[0][nt], af[0], b0, b1);
                    mma_f16(acc[1][nt], af[1], b0, b1);
                }
                if (do_logits) {
                    uint32_t alo[2][4];
#pragma unroll
                    for (int mt = 0; mt < 2; ++mt) {
                        float2 h0 = unpack_f16x2(af[mt][0]);
                        float2 h1 = unpack_f16x2(af[mt][1]);
                        float2 h2 = unpack_f16x2(af[mt][2]);
                        float2 h3 = unpack_f16x2(af[mt][3]);
                        alo[mt][0] = pack_f16x2(rawA[mt].x - h0.x, rawA[mt].y - h0.y);
                        alo[mt][1] = pack_f16x2(rawB[mt].x - h1.x, rawB[mt].y - h1.y);
                        alo[mt][2] = pack_f16x2(rawA[mt].z - h2.x, rawA[mt].w - h2.y);
                        alo[mt][3] = pack_f16x2(rawB[mt].z - h3.x, rawB[mt].w - h3.y);
                    }
                    uint32_t h0 = ks ? bh4.z : bh4.x, h1 = ks ? bh4.w : bh4.y;
                    uint32_t l0 = ks ? bl4.z : bl4.x, l1 = ks ? bl4.w : bl4.y;
                    mma_f16(acc[0][8], af[0], h0, h1);
                    mma_f16(acc[1][8], af[1], h0, h1);
                    mma_f16(acc[0][8], af[0], l0, l1);
                    mma_f16(acc[1][8], af[1], l0, l1);
                    mma_f16(acc[0][8], alo[0], h0, h1);
                    mma_f16(acc[1][8], alo[1], h0, h1);
                }
            }
        }
    }

    if (wn == 0) {
#pragma unroll
        for (int mt = 0; mt < 2; ++mt)
#pragma unroll
            for (int j = 0; j < 4; ++j)
                lbuf[((wm * 2 + mt) * 32 + lane) * 4 + j] = acc[mt][8][j];
    }
    __syncthreads();

    if (wn == 1) {
        const float rb0 = rb[2 * tig];
        const float rb1 = rb[2 * tig + 1];
#pragma unroll
        for (int mt = 0; mt < 2; ++mt) {
#pragma unroll
            for (int j = 0; j < 4; ++j)
                acc[mt][8][j] += lbuf[((wm * 2 + mt) * 32 + lane) * 4 + j];
#pragma unroll
            for (int half = 0; half < 2; ++half) {
                float l0 = acc[mt][8][half * 2 + 0] + rb0;
                float l1 = acc[mt][8][half * 2 + 1] + rb1;
                float m1, m2; int i1, i2;
                if (l0 >= l1) { m1 = l0; i1 = 2 * tig;     m2 = l1; i2 = 2 * tig + 1; }
                else          { m1 = l1; i1 = 2 * tig + 1; m2 = l0; i2 = 2 * tig; }
#pragma unroll
                for (int d = 1; d <= 2; d <<= 1) {
                    float om1 = __shfl_xor_sync(0xffffffffu, m1, d);
                    int   oi1 = __shfl_xor_sync(0xffffffffu, i1, d);
                    float om2 = __shfl_xor_sync(0xffffffffu, m2, d);
                    int   oi2 = __shfl_xor_sync(0xffffffffu, i2, d);
                    if (om1 > m1) {
                        if (m1 >= om2) { m2 = m1; i2 = i1; }
                        else           { m2 = om2; i2 = oi2; }
                        m1 = om1; i1 = oi1;
                    } else if (om1 > m2) { m2 = om1; i2 = oi1; }
                }
                float g1 = 1.f / (1.f + __expf(m2 - m1));
                float g2 = 1.f - g1;
                int row = wm * 32 + mt * 16 + half * 8 + g;
                gw[row * 8 + 2 * tig]     = (2 * tig     == i1) ? g1 : ((2 * tig     == i2) ? g2 : 0.f);
                gw[row * 8 + 2 * tig + 1] = (2 * tig + 1 == i1) ? g1 : ((2 * tig + 1 == i2) ? g2 : 0.f);
            }
        }
    }
    __syncthreads();

#pragma unroll
    for (int mt = 0; mt < 2; ++mt) {
#pragma unroll
        for (int nt = 0; nt < 8; ++nt) {
            const int col = ncol0 + nt * 8 + 2 * tig;
            const int e  = col >> 4;
            const int ra = wm * 32 + mt * 16 + g;
            const float wa = gw[ra * 8 + e];
            const float wb = gw[(ra + 8) * 8 + e];
            uint32_t w0 = pack_f16x2(acc[mt][nt][0] * wa, acc[mt][nt][1] * wa);
            uint32_t w1 = pack_f16x2(acc[mt][nt][2] * wb, acc[mt][nt][3] * wb);
            const int m16 = (m0 + wm * 32 + mt * 16) >> 4;
            const int k16 = wn * 4 + (nt >> 1);
            *(uint2*)(g_hwf + ((size_t)m16 * 8 + k16) * 128
                            + lane * 4 + 2 * (nt & 1)) = make_uint2(w0, w1);
        }
    }
}

// ============================================================================
// GEMM2: persistent grid-148 over 2048 pair-tiles. (unchanged from R14)
// ============================================================================
#define BS2_WORDS 8192
#define AP2_WORDS 16384
#define SM2_WORDS (BS2_WORDS + 2 * AP2_WORDS)
#define NPAIRS2   2048
#define GRID2     148

__global__ __launch_bounds__(256, 1)
void gemm2_kernel(float* __restrict__ out)
{
    extern __shared__ uint32_t smu[];
    uint32_t* Bs = smu;
    uint32_t* As = smu + BS2_WORDS;

    const int tid  = threadIdx.x;
    const int lane = tid & 31;
    const int warp = tid >> 5;
    const int wm   = warp & 3;
    const int wn   = warp >> 2;

    auto issueA = [&](int buf, int pt) {
        const size_t src = (size_t)(pt & 63) * 2 * 8192;
        uint32_t* dst = As + buf * AP2_WORDS;
#pragma unroll
        for (int i = 0; i < 16; i++) {
            int idx = tid + i * 256;
            cp16(dst + idx * 4, g_hwf + src + idx * 4);
        }
    };

    int p0 = (int)(((long long)blockIdx.x * NPAIRS2) / GRID2);
    const int p1 = (int)(((long long)(blockIdx.x + 1) * NPAIRS2) / GRID2);

    while (p0 < p1) {
        const int nb   = p0 >> 6;
        const int send = min(p1, (nb + 1) << 6);
        const int npl  = send - p0;
        const int n0   = nb * 128;

        __syncthreads();

        {
            const size_t bo = (size_t)nb * 8192;
#pragma unroll
            for (int i = 0; i < 8; i++) {
                int idx = tid + i * 256;
                cp16(Bs + idx * 4, g_btf + bo + idx * 4);
            }
        }
        issueA(0, p0);
        CP_COMMIT();
        if (npl > 1) issueA(1, p0 + 1);
        CP_COMMIT();

        for (int i = 0; i < npl; ++i) {
            const int pt = p0 + i;
            CP_WAIT(1);
            __syncthreads();

            const uint32_t* a0 = As + (i & 1) * AP2_WORDS;
            const uint32_t* a1 = a0 + 8192;

            float acc[4][8][4];
#pragma unroll
            for (int q = 0; q < 4; q++)
#pragma unroll
                for (int nt = 0; nt < 8; nt++)
#pragma unroll
                    for (int j = 0; j < 4; j++) acc[q][nt][j] = 0.f;

#pragma unroll
            for (int ks = 0; ks < 8; ++ks) {
                uint4 af[4];
#pragma unroll
                for (int mt = 0; mt < 2; mt++) {
                    af[mt]     = *(const uint4*)(a0 + ((wm * 2 + mt) * 8 + ks) * 128 + lane * 4);
                    af[2 + mt] = *(const uint4*)(a1 + ((wm * 2 + mt) * 8 + ks) * 128 + lane * 4);
                }
                uint2 bf[8];
#pragma unroll
                for (int nt = 0; nt < 8; nt++) {
                    const int n8l = wn * 8 + nt;
                    bf[nt] = *(const uint2*)(Bs + (n8l * 8 + ks) * 64 + lane * 2);
                }
#pragma unroll
                for (int nt = 0; nt < 8; nt++)
#pragma unroll
                    for (int q = 0; q < 4; q++)
                        mma_f16(acc[q][nt], (const uint32_t*)&af[q], bf[nt].x, bf[nt].y);
            }

            {
                const int g   = lane >> 2;
                const int tig = lane & 3;
#pragma unroll
                for (int tile = 0; tile < 2; ++tile) {
                    const int mbase = ((pt & 63) * 2 + tile) * 128;
#pragma unroll
                    for (int mt = 0; mt < 2; ++mt) {
#pragma unroll
                        for (int nt = 0; nt < 8; ++nt) {
                            const int col = n0 + wn * 64 + nt * 8 + 2 * tig;
                            const int ra  = mbase + wm * 32 + mt * 16 + g;
                            const float* av = acc[tile * 2 + mt][nt];
                            *(float2*)(out + (size_t)ra * OUT_D + col) =
                                make_float2(av[0], av[1]);
                            *(float2*)(out + (size_t)(ra + 8) * OUT_D + col) =
                                make_float2(av[2], av[3]);
                        }
                    }
                }
            }

            __syncthreads();
            if (i + 2 < npl) issueA(i & 1, pt + 2);
            CP_COMMIT();
        }
        p0 = send;
    }
}

// ============================================================================
extern "C" void kernel_launch(void* const* d_in, const int* in_sizes, int n_in,
                              void* d_out, int out_size)
{
    const float* x  = (const float*)d_in[0];   // [N, 4096]
    const float* rw = (const float*)d_in[1];   // [8, 4096]
    const float* rb = (const float*)d_in[2];   // [8]
    const float* A  = (const float*)d_in[3];   // [8,16,4096]
    const float* Bm = (const float*)d_in[4];   // [8,4096,16]
    float* out = (float*)d_out;                // [N, 4096] fp32

    const int sm1 = SM1_WORDS * 4;   // 212992 B
    const int sm2 = SM2_WORDS * 4;   // 163840 B
    cudaFuncSetAttribute(gemm1_kernel,
                         cudaFuncAttributeMaxDynamicSharedMemorySize, sm1);
    cudaFuncSetAttribute(gemm2_kernel,
                         cudaFuncAttributeMaxDynamicSharedMemorySize, sm2);

    prep_kernel<<<1024, 256>>>(rw, A, Bm);
    gemm1_kernel<<<N_TOK / 128, 256, sm1>>>(x, rb);
    gemm2_kernel<<<GRID2, 256, sm2>>>(out);
}